// round 1
// baseline (speedup 1.0000x reference)
#include <cuda_runtime.h>
#include <cuda_bf16.h>

// Problem constants
#define S_LEN 2048
#define BSZ   2
#define EMB   1024
#define NH    16
#define DH    64
#define MROWS (S_LEN*BSZ)      // 4096
#define NHEADS (BSZ*NH)        // 32

// Scratch (alloc-free rule: __device__ globals)
__device__ float g_Qp[MROWS*EMB];
__device__ float g_Kp[MROWS*EMB];
__device__ float g_Vp[MROWS*EMB];
__device__ float g_O [MROWS*EMB];
__device__ float g_attn[(size_t)NHEADS*S_LEN*S_LEN];   // 536 MB

// ---------------------------------------------------------------------------
// Generic tiled GEMM.
//   TRANSB=true : C[m,n] = scale*( sum_k A[m,k]*B[n,k] + bias[n] )   (A,W K-major)
//   TRANSB=false: C[m,n] = scale*( sum_k A[m,k]*B[k,n] + bias[n] )
// Batched over blockIdx.z with element strides.
// Requires: M%BM==0, N%BN==0, K%BK==0, lda/ldb multiples of 4, BK==16.
// ---------------------------------------------------------------------------
template<int BM,int BN,int BK,int TM,int TN,bool TRANSB>
__global__ __launch_bounds__(256)
void gemm_kernel(const float* __restrict__ A, int lda, long strideA,
                 const float* __restrict__ Bp, int ldb, long strideB,
                 float* __restrict__ C, int ldc, long strideC,
                 const float* __restrict__ bias, float scale,
                 int M, int N, int K)
{
    __shared__ __align__(16) float As[BK][BM];
    __shared__ __align__(16) float Bs[BK][BN];
    constexpr int NT = (BM/TM)*(BN/TN);   // 256 threads
    const int tid = threadIdx.x;
    const int tx  = tid % (BN/TN);
    const int ty  = tid / (BN/TN);
    const int m0  = blockIdx.y * BM;
    const int n0  = blockIdx.x * BN;
    const float* Az = A  + (long)blockIdx.z * strideA;
    const float* Bz = Bp + (long)blockIdx.z * strideB;
    float*       Cz = C  + (long)blockIdx.z * strideC;

    float acc[TM][TN] = {};

    for (int k0 = 0; k0 < K; k0 += BK) {
        // A tile [BM][BK] -> As[k][m] (transposed store)
        #pragma unroll
        for (int i = tid*4; i < BM*BK; i += NT*4) {
            int r = i / BK, c = i % BK;
            float4 v = *(const float4*)&Az[(long)(m0+r)*lda + k0 + c];
            As[c+0][r]=v.x; As[c+1][r]=v.y; As[c+2][r]=v.z; As[c+3][r]=v.w;
        }
        if (TRANSB) {
            // B tile [BN][BK] -> Bs[k][n]
            #pragma unroll
            for (int i = tid*4; i < BN*BK; i += NT*4) {
                int r = i / BK, c = i % BK;
                float4 v = *(const float4*)&Bz[(long)(n0+r)*ldb + k0 + c];
                Bs[c+0][r]=v.x; Bs[c+1][r]=v.y; Bs[c+2][r]=v.z; Bs[c+3][r]=v.w;
            }
        } else {
            // B tile [BK][BN] -> Bs[k][n] direct
            #pragma unroll
            for (int i = tid*4; i < BK*BN; i += NT*4) {
                int r = i / BN, c = i % BN;
                *(float4*)&Bs[r][c] = *(const float4*)&Bz[(long)(k0+r)*ldb + n0 + c];
            }
        }
        __syncthreads();
        #pragma unroll
        for (int kk = 0; kk < BK; ++kk) {
            float a[TM], b[TN];
            #pragma unroll
            for (int i = 0; i < TM; i += 4)
                *(float4*)&a[i] = *(const float4*)&As[kk][ty*TM + i];
            #pragma unroll
            for (int j = 0; j < TN; j += 4)
                *(float4*)&b[j] = *(const float4*)&Bs[kk][tx*TN + j];
            #pragma unroll
            for (int i = 0; i < TM; ++i)
                #pragma unroll
                for (int j = 0; j < TN; ++j)
                    acc[i][j] += a[i]*b[j];
        }
        __syncthreads();
    }

    #pragma unroll
    for (int i = 0; i < TM; ++i) {
        int m = m0 + ty*TM + i;
        #pragma unroll
        for (int j = 0; j < TN; ++j) {
            int n = n0 + tx*TN + j;
            float v = acc[i][j];
            if (bias) v += bias[n];
            Cz[(long)m*ldc + n] = v * scale;
        }
    }
}

// ---------------------------------------------------------------------------
// Row softmax over S_LEN=2048 elements, one block (256 thr) per row, in place.
// ---------------------------------------------------------------------------
__global__ __launch_bounds__(256)
void softmax_kernel(float* __restrict__ attn)
{
    float* p = attn + (long)blockIdx.x * S_LEN;
    const int tid = threadIdx.x;
    __shared__ float red[32];

    float vals[8];
    float m = -1e30f;
    #pragma unroll
    for (int i = 0; i < 8; ++i) { vals[i] = p[tid + i*256]; m = fmaxf(m, vals[i]); }

    #pragma unroll
    for (int o = 16; o > 0; o >>= 1) m = fmaxf(m, __shfl_xor_sync(0xffffffffu, m, o));
    if ((tid & 31) == 0) red[tid >> 5] = m;
    __syncthreads();
    if (tid < 32) {
        float t = (tid < 8) ? red[tid] : -1e30f;
        #pragma unroll
        for (int o = 4; o > 0; o >>= 1) t = fmaxf(t, __shfl_xor_sync(0xffffffffu, t, o));
        if (tid == 0) red[0] = t;
    }
    __syncthreads();
    m = red[0];
    __syncthreads();   // protect red[] before reuse

    float s = 0.f;
    #pragma unroll
    for (int i = 0; i < 8; ++i) { vals[i] = __expf(vals[i] - m); s += vals[i]; }

    #pragma unroll
    for (int o = 16; o > 0; o >>= 1) s += __shfl_xor_sync(0xffffffffu, s, o);
    if ((tid & 31) == 0) red[tid >> 5] = s;
    __syncthreads();
    if (tid < 32) {
        float t = (tid < 8) ? red[tid] : 0.f;
        #pragma unroll
        for (int o = 4; o > 0; o >>= 1) t += __shfl_xor_sync(0xffffffffu, t, o);
        if (tid == 0) red[0] = t;
    }
    __syncthreads();
    float inv = 1.0f / red[0];
    #pragma unroll
    for (int i = 0; i < 8; ++i) p[tid + i*256] = vals[i] * inv;
}

// ---------------------------------------------------------------------------
// attn_avg[b,q,k] = (1/H) * sum_h attn[(b*H+h), q, k]
// ---------------------------------------------------------------------------
__global__ __launch_bounds__(256)
void avg_kernel(const float* __restrict__ attn, float* __restrict__ out)
{
    long t = (long)blockIdx.x * blockDim.x + threadIdx.x;
    long b   = t / ((long)S_LEN*S_LEN);
    long rem = t - b*(long)S_LEN*S_LEN;
    const float* p = attn + b*NH*(long)S_LEN*S_LEN + rem;
    float s = 0.f;
    #pragma unroll
    for (int h = 0; h < NH; ++h) s += p[(long)h*S_LEN*S_LEN];
    out[t] = s * (1.0f/NH);
}

// ---------------------------------------------------------------------------
extern "C" void kernel_launch(void* const* d_in, const int* in_sizes, int n_in,
                              void* d_out, int out_size)
{
    const float* query = (const float*)d_in[0];
    const float* key   = (const float*)d_in[1];
    const float* value = (const float*)d_in[2];
    const float* q_w = (const float*)d_in[3];
    const float* q_b = (const float*)d_in[4];
    const float* k_w = (const float*)d_in[5];
    const float* k_b = (const float*)d_in[6];
    const float* v_w = (const float*)d_in[7];
    const float* v_b = (const float*)d_in[8];
    const float* out_w = (const float*)d_in[9];
    const float* out_b = (const float*)d_in[10];

    float *qp, *kp, *vp, *op, *attn;
    cudaGetSymbolAddress((void**)&qp,   g_Qp);
    cudaGetSymbolAddress((void**)&kp,   g_Kp);
    cudaGetSymbolAddress((void**)&vp,   g_Vp);
    cudaGetSymbolAddress((void**)&op,   g_O);
    cudaGetSymbolAddress((void**)&attn, g_attn);

    float* Z = (float*)d_out;                          // [S,B,E]
    float* attn_avg = (float*)d_out + (long)MROWS*EMB; // [B,S,S]

    const float scaling = 0.125f;   // D^-0.5 = 64^-0.5

    // 1) Projections: [4096,1024] = X @ W^T + b
    dim3 gproj(EMB/128, MROWS/128, 1);
    gemm_kernel<128,128,16,8,8,true><<<gproj,256>>>(
        query, EMB, 0, q_w, EMB, 0, qp, EMB, 0, q_b, scaling, MROWS, EMB, EMB);
    gemm_kernel<128,128,16,8,8,true><<<gproj,256>>>(
        key,   EMB, 0, k_w, EMB, 0, kp, EMB, 0, k_b, 1.0f,    MROWS, EMB, EMB);
    gemm_kernel<128,128,16,8,8,true><<<gproj,256>>>(
        value, EMB, 0, v_w, EMB, 0, vp, EMB, 0, v_b, 1.0f,    MROWS, EMB, EMB);

    // 2) Scores: per head bh, Q[q,:]·K[k,:]  (head base offset = bh*DH, row stride B*E)
    dim3 gsc(S_LEN/128, S_LEN/128, NHEADS);
    gemm_kernel<128,128,16,8,8,true><<<gsc,256>>>(
        qp, BSZ*EMB, DH, kp, BSZ*EMB, DH,
        attn, S_LEN, (long)S_LEN*S_LEN, nullptr, 1.0f, S_LEN, S_LEN, DH);

    // 3) Softmax rows
    softmax_kernel<<<NHEADS*S_LEN, 256>>>(attn);

    // 4) PV: out[q,d] = sum_k attn[q,k] * V[k,d]  -> written in [S,B,E] layout
    dim3 gav(DH/64, S_LEN/128, NHEADS);
    gemm_kernel<128,64,16,8,4,false><<<gav,256>>>(
        attn, S_LEN, (long)S_LEN*S_LEN, vp, BSZ*EMB, DH,
        op, BSZ*EMB, DH, nullptr, 1.0f, S_LEN, DH, S_LEN);

    // 5) Output projection -> Z
    gemm_kernel<128,128,16,8,8,true><<<gproj,256>>>(
        op, EMB, 0, out_w, EMB, 0, Z, EMB, 0, out_b, 1.0f, MROWS, EMB, EMB);

    // 6) Head-average of attention probs
    avg_kernel<<<(unsigned)(((long)BSZ*S_LEN*S_LEN)/256), 256>>>(attn, attn_avg);
}

// round 2
// speedup vs baseline: 2.3641x; 2.3641x over previous
#include <cuda_runtime.h>

#define S_LEN 2048
#define BSZ   2
#define EMB   1024
#define NH    16
#define DH    64
#define MROWS 4096
#define NHEADS 32
#define S2 ((long)S_LEN*S_LEN)

// Scratch (__device__ globals per alloc-free rule)
__device__ float g_Qp[MROWS*EMB];
__device__ float g_Kp[MROWS*EMB];
__device__ float g_VpT[EMB*MROWS];        // transposed V projection: [E][B][S]
__device__ float g_O [MROWS*EMB];
__device__ float g_attn[(size_t)NHEADS*S2];

__device__ __forceinline__ unsigned f2tf(float f){
    unsigned u; asm("cvt.rna.tf32.f32 %0, %1;" : "=r"(u) : "f"(f)); return u;
}
__device__ __forceinline__ void mma8(float* c, const unsigned* a, const unsigned* b){
    asm volatile("mma.sync.aligned.m16n8k8.row.col.f32.tf32.tf32.f32 "
      "{%0,%1,%2,%3}, {%4,%5,%6,%7}, {%8,%9}, {%0,%1,%2,%3};\n"
      : "+f"(c[0]), "+f"(c[1]), "+f"(c[2]), "+f"(c[3])
      : "r"(a[0]), "r"(a[1]), "r"(a[2]), "r"(a[3]), "r"(b[0]), "r"(b[1]));
}

// ---------------------------------------------------------------------------
// TN tf32 tensor-core GEMM: C[m,n] = scale*(sum_k A[m,k]*B[n,k] + bias[n])
// Both A and B are K-contiguous (row-major [rows][K]).
// Batched over blockIdx.z: per-operand offset = (z%16)*offH + (z/16)*offB.
// VT=true: write C transposed into VpT layout [n][m%2][m/2] (ldc ignored).
// Requires K % BK == 0, BK == 16.
// ---------------------------------------------------------------------------
template<int BM,int BN,int BK,int WM,int WN,int NWARPS,bool VT>
__global__ __launch_bounds__(NWARPS*32)
void mma_gemm(const float* __restrict__ A, int lda, long aH, long aB,
              const float* __restrict__ B, int ldb, long bH, long bB,
              float* __restrict__ C, int ldc, long cH, long cB,
              const float* __restrict__ bias, float scale, int K)
{
    constexpr int NT  = NWARPS*32;
    constexpr int LA  = BM*BK/(NT*4);
    constexpr int LB  = BN*BK/(NT*4);
    constexpr int WGN = BN/WN;
    constexpr int MI  = WM/16, NI = WN/8;
    constexpr int LDS_ = BK + 4;          // padded row (20 words): conflict-free frags

    __shared__ unsigned As[2][BM][LDS_];
    __shared__ unsigned Bs[2][BN][LDS_];

    const int tid  = threadIdx.x;
    const int lane = tid & 31, wid = tid >> 5;
    const int wm = wid / WGN, wn = wid % WGN;
    const int m0 = blockIdx.y * BM, n0 = blockIdx.x * BN;
    const int zh = blockIdx.z & (NH-1), zb = blockIdx.z >> 4;

    const float* Ag = A + zh*aH + zb*aB;
    const float* Bg = B + zh*bH + zb*bB;
    float*       Cg = C + zh*cH + zb*cB;

    float acc[MI][NI][4] = {};
    float4 ra[LA], rb[LB];

    auto ldtiles = [&](int k0){
        #pragma unroll
        for (int i = 0; i < LA; ++i){
            int idx = tid + i*NT;
            int r = idx / (BK/4), c = (idx % (BK/4)) * 4;
            ra[i] = *(const float4*)(Ag + (long)(m0+r)*lda + k0 + c);
        }
        #pragma unroll
        for (int i = 0; i < LB; ++i){
            int idx = tid + i*NT;
            int r = idx / (BK/4), c = (idx % (BK/4)) * 4;
            rb[i] = *(const float4*)(Bg + (long)(n0+r)*ldb + k0 + c);
        }
    };
    auto sttiles = [&](int buf){
        #pragma unroll
        for (int i = 0; i < LA; ++i){
            int idx = tid + i*NT;
            int r = idx / (BK/4), c = (idx % (BK/4)) * 4;
            uint4 u = { f2tf(ra[i].x), f2tf(ra[i].y), f2tf(ra[i].z), f2tf(ra[i].w) };
            *(uint4*)&As[buf][r][c] = u;
        }
        #pragma unroll
        for (int i = 0; i < LB; ++i){
            int idx = tid + i*NT;
            int r = idx / (BK/4), c = (idx % (BK/4)) * 4;
            uint4 u = { f2tf(rb[i].x), f2tf(rb[i].y), f2tf(rb[i].z), f2tf(rb[i].w) };
            *(uint4*)&Bs[buf][r][c] = u;
        }
    };
    auto compute = [&](int buf){
        #pragma unroll
        for (int ks = 0; ks < BK/8; ++ks){
            unsigned af[MI][4], bf[NI][2];
            #pragma unroll
            for (int mi = 0; mi < MI; ++mi){
                int m = wm*WM + mi*16 + (lane>>2);
                int k = ks*8 + (lane&3);
                af[mi][0] = As[buf][m  ][k  ];
                af[mi][1] = As[buf][m+8][k  ];
                af[mi][2] = As[buf][m  ][k+4];
                af[mi][3] = As[buf][m+8][k+4];
            }
            #pragma unroll
            for (int ni = 0; ni < NI; ++ni){
                int n = wn*WN + ni*8 + (lane>>2);
                int k = ks*8 + (lane&3);
                bf[ni][0] = Bs[buf][n][k  ];
                bf[ni][1] = Bs[buf][n][k+4];
            }
            #pragma unroll
            for (int mi = 0; mi < MI; ++mi)
                #pragma unroll
                for (int ni = 0; ni < NI; ++ni)
                    mma8(acc[mi][ni], af[mi], bf[ni]);
        }
    };

    ldtiles(0); sttiles(0); __syncthreads();
    const int nk = K/BK;
    for (int t = 1; t < nk; ++t){
        ldtiles(t*BK);
        compute((t-1)&1);
        sttiles(t&1);
        __syncthreads();
    }
    compute((nk-1)&1);

    #pragma unroll
    for (int mi = 0; mi < MI; ++mi){
        #pragma unroll
        for (int ni = 0; ni < NI; ++ni){
            int m = m0 + wm*WM + mi*16 + (lane>>2);
            int n = n0 + wn*WN + ni*8 + 2*(lane&3);
            float v0 = acc[mi][ni][0], v1 = acc[mi][ni][1];
            float v2 = acc[mi][ni][2], v3 = acc[mi][ni][3];
            if (bias){ float b0 = bias[n], b1 = bias[n+1];
                       v0 += b0; v1 += b1; v2 += b0; v3 += b1; }
            v0 *= scale; v1 *= scale; v2 *= scale; v3 *= scale;
            if (VT){
                int s0 = (m&1)*S_LEN + (m>>1);
                int m2 = m + 8;
                int s2 = (m2&1)*S_LEN + (m2>>1);
                Cg[(long)n    *MROWS + s0] = v0;
                Cg[(long)(n+1)*MROWS + s0] = v1;
                Cg[(long)n    *MROWS + s2] = v2;
                Cg[(long)(n+1)*MROWS + s2] = v3;
            } else {
                *(float2*)(Cg + (long)m    *ldc + n) = make_float2(v0, v1);
                *(float2*)(Cg + (long)(m+8)*ldc + n) = make_float2(v2, v3);
            }
        }
    }
}

// ---------------------------------------------------------------------------
// Row softmax over 2048 elems, one 256-thread block per row, in place.
// ---------------------------------------------------------------------------
__global__ __launch_bounds__(256)
void softmax_kernel(float* __restrict__ attn)
{
    float* p = attn + (long)blockIdx.x * S_LEN;
    const int tid = threadIdx.x;
    __shared__ float red[32];

    float vals[8];
    float m = -1e30f;
    #pragma unroll
    for (int i = 0; i < 8; ++i) { vals[i] = p[tid + i*256]; m = fmaxf(m, vals[i]); }

    #pragma unroll
    for (int o = 16; o > 0; o >>= 1) m = fmaxf(m, __shfl_xor_sync(0xffffffffu, m, o));
    if ((tid & 31) == 0) red[tid >> 5] = m;
    __syncthreads();
    if (tid < 32) {
        float t = (tid < 8) ? red[tid] : -1e30f;
        #pragma unroll
        for (int o = 4; o > 0; o >>= 1) t = fmaxf(t, __shfl_xor_sync(0xffffffffu, t, o));
        if (tid == 0) red[0] = t;
    }
    __syncthreads();
    m = red[0];
    __syncthreads();

    float s = 0.f;
    #pragma unroll
    for (int i = 0; i < 8; ++i) { vals[i] = __expf(vals[i] - m); s += vals[i]; }

    #pragma unroll
    for (int o = 16; o > 0; o >>= 1) s += __shfl_xor_sync(0xffffffffu, s, o);
    if ((tid & 31) == 0) red[tid >> 5] = s;
    __syncthreads();
    if (tid < 32) {
        float t = (tid < 8) ? red[tid] : 0.f;
        #pragma unroll
        for (int o = 4; o > 0; o >>= 1) t += __shfl_xor_sync(0xffffffffu, t, o);
        if (tid == 0) red[0] = t;
    }
    __syncthreads();
    float inv = 1.0f / red[0];
    #pragma unroll
    for (int i = 0; i < 8; ++i) p[tid + i*256] = vals[i] * inv;
}

// ---------------------------------------------------------------------------
// attn_avg[b,q,k] = (1/16) * sum_h attn[(b*16+h), q, k]  (float4 vectorized)
// ---------------------------------------------------------------------------
__global__ __launch_bounds__(256)
void avg_kernel(const float4* __restrict__ attn, float4* __restrict__ out)
{
    long t = (long)blockIdx.x * blockDim.x + threadIdx.x;
    const long per = S2/4;
    long b   = t / per;
    long rem = t - b*per;
    const float4* p = attn + b*NH*per + rem;
    float4 s = make_float4(0.f,0.f,0.f,0.f);
    #pragma unroll
    for (int h = 0; h < NH; ++h){
        float4 v = p[(long)h*per];
        s.x += v.x; s.y += v.y; s.z += v.z; s.w += v.w;
    }
    const float inv = 1.0f/NH;
    s.x *= inv; s.y *= inv; s.z *= inv; s.w *= inv;
    out[t] = s;
}

// ---------------------------------------------------------------------------
extern "C" void kernel_launch(void* const* d_in, const int* in_sizes, int n_in,
                              void* d_out, int out_size)
{
    const float* query = (const float*)d_in[0];
    const float* key   = (const float*)d_in[1];
    const float* value = (const float*)d_in[2];
    const float* q_w = (const float*)d_in[3];
    const float* q_b = (const float*)d_in[4];
    const float* k_w = (const float*)d_in[5];
    const float* k_b = (const float*)d_in[6];
    const float* v_w = (const float*)d_in[7];
    const float* v_b = (const float*)d_in[8];
    const float* out_w = (const float*)d_in[9];
    const float* out_b = (const float*)d_in[10];

    float *qp, *kp, *vpT, *op, *attn;
    cudaGetSymbolAddress((void**)&qp,   g_Qp);
    cudaGetSymbolAddress((void**)&kp,   g_Kp);
    cudaGetSymbolAddress((void**)&vpT,  g_VpT);
    cudaGetSymbolAddress((void**)&op,   g_O);
    cudaGetSymbolAddress((void**)&attn, g_attn);

    float* Z = (float*)d_out;                          // [S,B,E]
    float* attn_avg = (float*)d_out + (long)MROWS*EMB; // [B,S,S]

    const float scaling = 0.125f;   // 64^-0.5

    // 1) Projections [4096x1024] = X @ W^T + b   (TN, tf32 MMA)
    dim3 gproj(EMB/128, MROWS/128, 1);
    mma_gemm<128,128,16,64,32,8,false><<<gproj,256>>>(
        query, EMB, 0,0, q_w, EMB, 0,0, qp, EMB, 0,0, q_b, scaling, EMB);
    mma_gemm<128,128,16,64,32,8,false><<<gproj,256>>>(
        key,   EMB, 0,0, k_w, EMB, 0,0, kp, EMB, 0,0, k_b, 1.0f,    EMB);
    // V projection written transposed -> VpT[E][B][S]
    mma_gemm<128,128,16,64,32,8,true><<<gproj,256>>>(
        value, EMB, 0,0, v_w, EMB, 0,0, vpT, 0, 0,0, v_b, 1.0f,     EMB);

    // 2) Scores: per head z=b*16+h, Q·K^T  (offsets: h*64 + b*1024)
    dim3 gsc(S_LEN/128, S_LEN/128, NHEADS);
    mma_gemm<128,128,16,64,32,8,false><<<gsc,256>>>(
        qp, BSZ*EMB, DH, EMB,
        kp, BSZ*EMB, DH, EMB,
        attn, S_LEN, S2, NH*S2, nullptr, 1.0f, DH);

    // 3) Softmax rows
    softmax_kernel<<<NHEADS*S_LEN, 256>>>(attn);

    // 4) PV: out[q,d] = sum_k P[q,k] * VpT[d,k]  (TN via transposed V)
    dim3 gpv(1, S_LEN/128, NHEADS);
    mma_gemm<128,64,16,32,32,8,false><<<gpv,256>>>(
        attn, S_LEN, S2, NH*S2,
        vpT, MROWS, (long)DH*MROWS, S_LEN,
        op, BSZ*EMB, DH, EMB, nullptr, 1.0f, S_LEN);

    // 5) Output projection -> Z
    mma_gemm<128,128,16,64,32,8,false><<<gproj,256>>>(
        op, EMB, 0,0, out_w, EMB, 0,0, Z, EMB, 0,0, out_b, 1.0f, EMB);

    // 6) Head-average of attention probs
    avg_kernel<<<(unsigned)((BSZ*S2/4)/256), 256>>>((const float4*)attn, (float4*)attn_avg);
}

// round 3
// speedup vs baseline: 2.5366x; 1.0730x over previous
#include <cuda_runtime.h>

#define S_LEN 2048
#define BSZ   2
#define EMB   1024
#define NH    16
#define DH    64
#define MROWS 4096
#define NHEADS 32
#define S2 ((long)S_LEN*S_LEN)

// Scratch (__device__ globals per alloc-free rule)
__device__ float g_Qp[MROWS*EMB];
__device__ float g_Kp[MROWS*EMB];
__device__ float g_Vp[MROWS*EMB];
__device__ float g_O [MROWS*EMB];
__device__ float g_m [NHEADS*S_LEN];
__device__ float g_l [NHEADS*S_LEN];

__device__ __forceinline__ unsigned f2tf(float f){
    unsigned u; asm("cvt.rna.tf32.f32 %0, %1;" : "=r"(u) : "f"(f)); return u;
}
__device__ __forceinline__ void mma8(float* c, const unsigned* a, const unsigned* b){
    asm volatile("mma.sync.aligned.m16n8k8.row.col.f32.tf32.tf32.f32 "
      "{%0,%1,%2,%3}, {%4,%5,%6,%7}, {%8,%9}, {%0,%1,%2,%3};\n"
      : "+f"(c[0]), "+f"(c[1]), "+f"(c[2]), "+f"(c[3])
      : "r"(a[0]), "r"(a[1]), "r"(a[2]), "r"(a[3]), "r"(b[0]), "r"(b[1]));
}

// ---------------------------------------------------------------------------
// TN tf32 GEMM for the 4 projections (proven in round 2).
// C[m,n] = scale*(sum_k A[m,k]*B[n,k] + bias[n])
// ---------------------------------------------------------------------------
template<int BM,int BN,int BK,int WM,int WN,int NWARPS>
__global__ __launch_bounds__(NWARPS*32)
void mma_gemm(const float* __restrict__ A, int lda,
              const float* __restrict__ B, int ldb,
              float* __restrict__ C, int ldc,
              const float* __restrict__ bias, float scale, int K)
{
    constexpr int NT  = NWARPS*32;
    constexpr int LA  = BM*BK/(NT*4);
    constexpr int LB  = BN*BK/(NT*4);
    constexpr int WGN = BN/WN;
    constexpr int MI  = WM/16, NI = WN/8;
    constexpr int LDS_ = BK + 4;

    __shared__ unsigned As[2][BM][LDS_];
    __shared__ unsigned Bs[2][BN][LDS_];

    const int tid  = threadIdx.x;
    const int lane = tid & 31, wid = tid >> 5;
    const int wm = wid / WGN, wn = wid % WGN;
    const int m0 = blockIdx.y * BM, n0 = blockIdx.x * BN;

    float acc[MI][NI][4] = {};
    float4 ra[LA], rb[LB];

    auto ldtiles = [&](int k0){
        #pragma unroll
        for (int i = 0; i < LA; ++i){
            int idx = tid + i*NT;
            int r = idx / (BK/4), c = (idx % (BK/4)) * 4;
            ra[i] = *(const float4*)(A + (long)(m0+r)*lda + k0 + c);
        }
        #pragma unroll
        for (int i = 0; i < LB; ++i){
            int idx = tid + i*NT;
            int r = idx / (BK/4), c = (idx % (BK/4)) * 4;
            rb[i] = *(const float4*)(B + (long)(n0+r)*ldb + k0 + c);
        }
    };
    auto sttiles = [&](int buf){
        #pragma unroll
        for (int i = 0; i < LA; ++i){
            int idx = tid + i*NT;
            int r = idx / (BK/4), c = (idx % (BK/4)) * 4;
            uint4 u = { f2tf(ra[i].x), f2tf(ra[i].y), f2tf(ra[i].z), f2tf(ra[i].w) };
            *(uint4*)&As[buf][r][c] = u;
        }
        #pragma unroll
        for (int i = 0; i < LB; ++i){
            int idx = tid + i*NT;
            int r = idx / (BK/4), c = (idx % (BK/4)) * 4;
            uint4 u = { f2tf(rb[i].x), f2tf(rb[i].y), f2tf(rb[i].z), f2tf(rb[i].w) };
            *(uint4*)&Bs[buf][r][c] = u;
        }
    };
    auto compute = [&](int buf){
        #pragma unroll
        for (int ks = 0; ks < BK/8; ++ks){
            unsigned af[MI][4], bf[NI][2];
            #pragma unroll
            for (int mi = 0; mi < MI; ++mi){
                int m = wm*WM + mi*16 + (lane>>2);
                int k = ks*8 + (lane&3);
                af[mi][0] = As[buf][m  ][k  ];
                af[mi][1] = As[buf][m+8][k  ];
                af[mi][2] = As[buf][m  ][k+4];
                af[mi][3] = As[buf][m+8][k+4];
            }
            #pragma unroll
            for (int ni = 0; ni < NI; ++ni){
                int n = wn*WN + ni*8 + (lane>>2);
                int k = ks*8 + (lane&3);
                bf[ni][0] = Bs[buf][n][k  ];
                bf[ni][1] = Bs[buf][n][k+4];
            }
            #pragma unroll
            for (int mi = 0; mi < MI; ++mi)
                #pragma unroll
                for (int ni = 0; ni < NI; ++ni)
                    mma8(acc[mi][ni], af[mi], bf[ni]);
        }
    };

    ldtiles(0); sttiles(0); __syncthreads();
    const int nk = K/BK;
    for (int t = 1; t < nk; ++t){
        ldtiles(t*BK);
        compute((t-1)&1);
        sttiles(t&1);
        __syncthreads();
    }
    compute((nk-1)&1);

    #pragma unroll
    for (int mi = 0; mi < MI; ++mi){
        #pragma unroll
        for (int ni = 0; ni < NI; ++ni){
            int m = m0 + wm*WM + mi*16 + (lane>>2);
            int n = n0 + wn*WN + ni*8 + 2*(lane&3);
            float v0 = acc[mi][ni][0], v1 = acc[mi][ni][1];
            float v2 = acc[mi][ni][2], v3 = acc[mi][ni][3];
            if (bias){ float b0 = bias[n], b1 = bias[n+1];
                       v0 += b0; v1 += b1; v2 += b0; v3 += b1; }
            v0 *= scale; v1 *= scale; v2 *= scale; v3 *= scale;
            *(float2*)(C + (long)m    *ldc + n) = make_float2(v0, v1);
            *(float2*)(C + (long)(m+8)*ldc + n) = make_float2(v2, v3);
        }
    }
}

// ---------------------------------------------------------------------------
// Flash attention: block = (head-batch hb, q-tile of 64). 4 warps, 128 thr.
// Warp owns 16 q rows. K/V tiles of 64 staged in smem (tf32). Online softmax.
// Writes O (in [S][B][E] layout) and per-row m,l stats.
// ---------------------------------------------------------------------------
__global__ __launch_bounds__(128)
void flash_attn(const float* __restrict__ qp, const float* __restrict__ kp,
                const float* __restrict__ vp, float* __restrict__ op,
                float* __restrict__ gm, float* __restrict__ gl)
{
    constexpr int PAD = 68;
    __shared__ unsigned Ks[64*PAD];
    __shared__ unsigned Vs[64*PAD];
    const int tid = threadIdx.x, lane = tid&31, w = tid>>5;
    const int hb = blockIdx.x;          // = b*16 + h
    const int h  = hb & 15, b = hb >> 4;
    const int q0 = blockIdx.y * 64;
    const long base = (long)b*EMB + h*DH;   // elem (s,d) at s*2048 + base + d

    // stage Q tile into Ks (temporarily), converted to tf32
    const float* Qg = qp + base;
    for (int i = tid; i < 64*16; i += 128){
        int r = i>>4, c = (i&15)*4;
        float4 v = *(const float4*)(Qg + (long)(q0+r)*(BSZ*EMB) + c);
        unsigned* dst = &Ks[r*PAD + c];
        dst[0]=f2tf(v.x); dst[1]=f2tf(v.y); dst[2]=f2tf(v.z); dst[3]=f2tf(v.w);
    }
    __syncthreads();
    // Q A-fragments live in registers for the whole kernel
    unsigned Qa[8][4];
    const int r0 = w*16 + (lane>>2);
    #pragma unroll
    for (int ks = 0; ks < 8; ++ks){
        int k = ks*8 + (lane&3);
        Qa[ks][0] = Ks[ r0   *PAD + k    ];
        Qa[ks][1] = Ks[(r0+8)*PAD + k    ];
        Qa[ks][2] = Ks[ r0   *PAD + k + 4];
        Qa[ks][3] = Ks[(r0+8)*PAD + k + 4];
    }
    __syncthreads();

    float m0 = -1e30f, m1 = -1e30f, l0 = 0.f, l1 = 0.f;
    float o[8][4] = {};

    const float* Kg = kp + base;
    const float* Vg = vp + base;

    for (int kt = 0; kt < S_LEN/64; ++kt){
        const int k0 = kt*64;
        for (int i = tid; i < 64*16; i += 128){
            int r = i>>4, c = (i&15)*4;
            float4 vk = *(const float4*)(Kg + (long)(k0+r)*(BSZ*EMB) + c);
            float4 vv = *(const float4*)(Vg + (long)(k0+r)*(BSZ*EMB) + c);
            unsigned* dk = &Ks[r*PAD + c];
            dk[0]=f2tf(vk.x); dk[1]=f2tf(vk.y); dk[2]=f2tf(vk.z); dk[3]=f2tf(vk.w);
            unsigned* dv = &Vs[r*PAD + c];
            dv[0]=f2tf(vv.x); dv[1]=f2tf(vv.y); dv[2]=f2tf(vv.z); dv[3]=f2tf(vv.w);
        }
        __syncthreads();

        // S = Q K^T  (warp tile 16 x 64)
        float c_[8][4] = {};
        #pragma unroll
        for (int ks = 0; ks < 8; ++ks){
            #pragma unroll
            for (int ni = 0; ni < 8; ++ni){
                unsigned bf[2];
                int n = ni*8 + (lane>>2);
                int k = ks*8 + (lane&3);
                bf[0] = Ks[n*PAD + k];
                bf[1] = Ks[n*PAD + k + 4];
                mma8(c_[ni], Qa[ks], bf);
            }
        }

        // online softmax (rows r0 and r0+8; row spans the 4-lane quad)
        float mx0 = -1e30f, mx1 = -1e30f;
        #pragma unroll
        for (int ni = 0; ni < 8; ++ni){
            mx0 = fmaxf(mx0, fmaxf(c_[ni][0], c_[ni][1]));
            mx1 = fmaxf(mx1, fmaxf(c_[ni][2], c_[ni][3]));
        }
        mx0 = fmaxf(mx0, __shfl_xor_sync(0xffffffffu, mx0, 1));
        mx0 = fmaxf(mx0, __shfl_xor_sync(0xffffffffu, mx0, 2));
        mx1 = fmaxf(mx1, __shfl_xor_sync(0xffffffffu, mx1, 1));
        mx1 = fmaxf(mx1, __shfl_xor_sync(0xffffffffu, mx1, 2));
        float mn0 = fmaxf(m0, mx0), mn1 = fmaxf(m1, mx1);
        float f0 = __expf(m0 - mn0), f1 = __expf(m1 - mn1);
        l0 *= f0; l1 *= f1;
        #pragma unroll
        for (int ni = 0; ni < 8; ++ni){
            o[ni][0]*=f0; o[ni][1]*=f0; o[ni][2]*=f1; o[ni][3]*=f1;
        }
        float s0 = 0.f, s1 = 0.f;
        #pragma unroll
        for (int ni = 0; ni < 8; ++ni){
            c_[ni][0] = __expf(c_[ni][0]-mn0); c_[ni][1] = __expf(c_[ni][1]-mn0);
            c_[ni][2] = __expf(c_[ni][2]-mn1); c_[ni][3] = __expf(c_[ni][3]-mn1);
            s0 += c_[ni][0]+c_[ni][1]; s1 += c_[ni][2]+c_[ni][3];
        }
        s0 += __shfl_xor_sync(0xffffffffu, s0, 1);
        s0 += __shfl_xor_sync(0xffffffffu, s0, 2);
        s1 += __shfl_xor_sync(0xffffffffu, s1, 1);
        s1 += __shfl_xor_sync(0xffffffffu, s1, 2);
        l0 += s0; l1 += s1; m0 = mn0; m1 = mn1;

        // convert P C-fragments to A-fragments via quad shuffle, then P@V
        const int q  = lane & 3;
        const int srcA = (lane & ~3) | (q>>1);
        const int srcB = srcA + 2;
        #pragma unroll
        for (int ks2 = 0; ks2 < 8; ++ks2){
            float v00 = __shfl_sync(0xffffffffu, c_[ks2][0], srcA);
            float v01 = __shfl_sync(0xffffffffu, c_[ks2][1], srcA);
            float v10 = __shfl_sync(0xffffffffu, c_[ks2][2], srcA);
            float v11 = __shfl_sync(0xffffffffu, c_[ks2][3], srcA);
            float v40 = __shfl_sync(0xffffffffu, c_[ks2][0], srcB);
            float v41 = __shfl_sync(0xffffffffu, c_[ks2][1], srcB);
            float v50 = __shfl_sync(0xffffffffu, c_[ks2][2], srcB);
            float v51 = __shfl_sync(0xffffffffu, c_[ks2][3], srcB);
            unsigned a[4];
            a[0] = f2tf((q&1) ? v01 : v00);
            a[1] = f2tf((q&1) ? v11 : v10);
            a[2] = f2tf((q&1) ? v41 : v40);
            a[3] = f2tf((q&1) ? v51 : v50);
            #pragma unroll
            for (int ni = 0; ni < 8; ++ni){
                unsigned bf[2];
                int kk = ks2*8 + (lane&3);
                int n  = ni*8 + (lane>>2);
                bf[0] = Vs[ kk   *PAD + n];
                bf[1] = Vs[(kk+4)*PAD + n];
                mma8(o[ni], a, bf);
            }
        }
        __syncthreads();
    }

    // finalize: normalize and write O; store row stats
    float inv0 = 1.f/l0, inv1 = 1.f/l1;
    float* Og = op + base;
    #pragma unroll
    for (int ni = 0; ni < 8; ++ni){
        int d = ni*8 + 2*(lane&3);
        *(float2*)(Og + (long)(q0+r0)  *(BSZ*EMB) + d) = make_float2(o[ni][0]*inv0, o[ni][1]*inv0);
        *(float2*)(Og + (long)(q0+r0+8)*(BSZ*EMB) + d) = make_float2(o[ni][2]*inv1, o[ni][3]*inv1);
    }
    if ((lane & 3) == 0){
        gm[(long)hb*S_LEN + q0 + r0]     = m0;
        gm[(long)hb*S_LEN + q0 + r0 + 8] = m1;
        gl[(long)hb*S_LEN + q0 + r0]     = l0;
        gl[(long)hb*S_LEN + q0 + r0 + 8] = l1;
    }
}

// ---------------------------------------------------------------------------
// attn_avg: block = (k-tile 64, q-tile 64, batch). Loops 16 heads, recomputes
// QK^T with tf32 MMA, applies exp(s-m)/l from stored stats, sums heads in
// registers, writes avg tile once.
// ---------------------------------------------------------------------------
__global__ __launch_bounds__(128)
void avg_attn(const float* __restrict__ qp, const float* __restrict__ kp,
              const float* __restrict__ gm, const float* __restrict__ gl,
              float* __restrict__ avg)
{
    constexpr int PAD = 68;
    __shared__ unsigned Qs[64*PAD];
    __shared__ unsigned Ks[64*PAD];
    const int tid = threadIdx.x, lane = tid&31, w = tid>>5;
    const int k0 = blockIdx.x*64, q0 = blockIdx.y*64, b = blockIdx.z;
    const int r0 = w*16 + (lane>>2);

    float acc[8][4] = {};

    for (int h = 0; h < NH; ++h){
        const long base = (long)b*EMB + h*DH;
        const float* Qg = qp + base;
        const float* Kg = kp + base;
        for (int i = tid; i < 64*16; i += 128){
            int r = i>>4, c = (i&15)*4;
            float4 vq = *(const float4*)(Qg + (long)(q0+r)*(BSZ*EMB) + c);
            float4 vk = *(const float4*)(Kg + (long)(k0+r)*(BSZ*EMB) + c);
            unsigned* dq = &Qs[r*PAD + c];
            dq[0]=f2tf(vq.x); dq[1]=f2tf(vq.y); dq[2]=f2tf(vq.z); dq[3]=f2tf(vq.w);
            unsigned* dk = &Ks[r*PAD + c];
            dk[0]=f2tf(vk.x); dk[1]=f2tf(vk.y); dk[2]=f2tf(vk.z); dk[3]=f2tf(vk.w);
        }
        __syncthreads();

        float c_[8][4] = {};
        #pragma unroll
        for (int ks = 0; ks < 8; ++ks){
            unsigned a[4];
            int k = ks*8 + (lane&3);
            a[0] = Qs[ r0   *PAD + k    ];
            a[1] = Qs[(r0+8)*PAD + k    ];
            a[2] = Qs[ r0   *PAD + k + 4];
            a[3] = Qs[(r0+8)*PAD + k + 4];
            #pragma unroll
            for (int ni = 0; ni < 8; ++ni){
                unsigned bf[2];
                int n = ni*8 + (lane>>2);
                bf[0] = Ks[n*PAD + k];
                bf[1] = Ks[n*PAD + k + 4];
                mma8(c_[ni], a, bf);
            }
        }

        const int hb = b*NH + h;
        float mm0 = gm[(long)hb*S_LEN + q0 + r0];
        float mm1 = gm[(long)hb*S_LEN + q0 + r0 + 8];
        float il0 = 1.f / gl[(long)hb*S_LEN + q0 + r0];
        float il1 = 1.f / gl[(long)hb*S_LEN + q0 + r0 + 8];
        #pragma unroll
        for (int ni = 0; ni < 8; ++ni){
            acc[ni][0] += __expf(c_[ni][0]-mm0)*il0;
            acc[ni][1] += __expf(c_[ni][1]-mm0)*il0;
            acc[ni][2] += __expf(c_[ni][2]-mm1)*il1;
            acc[ni][3] += __expf(c_[ni][3]-mm1)*il1;
        }
        __syncthreads();
    }

    float* out = avg + (long)b*S2;
    const float s = 1.0f/NH;
    #pragma unroll
    for (int ni = 0; ni < 8; ++ni){
        int kc = k0 + ni*8 + 2*(lane&3);
        *(float2*)(out + (long)(q0+r0)  *S_LEN + kc) = make_float2(acc[ni][0]*s, acc[ni][1]*s);
        *(float2*)(out + (long)(q0+r0+8)*S_LEN + kc) = make_float2(acc[ni][2]*s, acc[ni][3]*s);
    }
}

// ---------------------------------------------------------------------------
extern "C" void kernel_launch(void* const* d_in, const int* in_sizes, int n_in,
                              void* d_out, int out_size)
{
    const float* query = (const float*)d_in[0];
    const float* key   = (const float*)d_in[1];
    const float* value = (const float*)d_in[2];
    const float* q_w = (const float*)d_in[3];
    const float* q_b = (const float*)d_in[4];
    const float* k_w = (const float*)d_in[5];
    const float* k_b = (const float*)d_in[6];
    const float* v_w = (const float*)d_in[7];
    const float* v_b = (const float*)d_in[8];
    const float* out_w = (const float*)d_in[9];
    const float* out_b = (const float*)d_in[10];

    float *qp, *kp, *vp, *op, *gm, *gl;
    cudaGetSymbolAddress((void**)&qp, g_Qp);
    cudaGetSymbolAddress((void**)&kp, g_Kp);
    cudaGetSymbolAddress((void**)&vp, g_Vp);
    cudaGetSymbolAddress((void**)&op, g_O);
    cudaGetSymbolAddress((void**)&gm, g_m);
    cudaGetSymbolAddress((void**)&gl, g_l);

    float* Z = (float*)d_out;                          // [S,B,E]
    float* attn_avg = (float*)d_out + (long)MROWS*EMB; // [B,S,S]

    const float scaling = 0.125f;   // 64^-0.5

    // 1) Projections [4096x1024] = X @ W^T + b
    dim3 gproj(EMB/128, MROWS/128, 1);
    mma_gemm<128,128,16,64,32,8><<<gproj,256>>>(query, EMB, q_w, EMB, qp, EMB, q_b, scaling, EMB);
    mma_gemm<128,128,16,64,32,8><<<gproj,256>>>(key,   EMB, k_w, EMB, kp, EMB, k_b, 1.0f,    EMB);
    mma_gemm<128,128,16,64,32,8><<<gproj,256>>>(value, EMB, v_w, EMB, vp, EMB, v_b, 1.0f,    EMB);

    // 2) Flash attention: O + softmax stats (no attn matrix materialization)
    dim3 gfa(NHEADS, S_LEN/64, 1);
    flash_attn<<<gfa, 128>>>(qp, kp, vp, op, gm, gl);

    // 3) Output projection -> Z
    mma_gemm<128,128,16,64,32,8><<<gproj,256>>>(op, EMB, out_w, EMB, Z, EMB, out_b, 1.0f, EMB);

    // 4) attn_avg by QK^T recompute + stored stats
    dim3 gav(S_LEN/64, S_LEN/64, BSZ);
    avg_attn<<<gav, 128>>>(qp, kp, gm, gl, attn_avg);
}

// round 4
// speedup vs baseline: 2.7076x; 1.0674x over previous
#include <cuda_runtime.h>

#define S_LEN 2048
#define BSZ   2
#define EMB   1024
#define NH    16
#define DH    64
#define MROWS 4096
#define NHEADS 32
#define S2 ((long)S_LEN*S_LEN)

// Scratch (__device__ globals per alloc-free rule)
__device__ float g_Qp[MROWS*EMB];
__device__ float g_Kp[MROWS*EMB];
__device__ float g_Vp[MROWS*EMB];
__device__ float g_O [MROWS*EMB];
__device__ float g_m [NHEADS*S_LEN];
__device__ float g_l [NHEADS*S_LEN];

__device__ __forceinline__ unsigned f2tf(float f){
    unsigned u; asm("cvt.rna.tf32.f32 %0, %1;" : "=r"(u) : "f"(f)); return u;
}
__device__ __forceinline__ void mma8(float* c, const unsigned* a, const unsigned* b){
    asm volatile("mma.sync.aligned.m16n8k8.row.col.f32.tf32.tf32.f32 "
      "{%0,%1,%2,%3}, {%4,%5,%6,%7}, {%8,%9}, {%0,%1,%2,%3};\n"
      : "+f"(c[0]), "+f"(c[1]), "+f"(c[2]), "+f"(c[3])
      : "r"(a[0]), "r"(a[1]), "r"(a[2]), "r"(a[3]), "r"(b[0]), "r"(b[1]));
}
__device__ __forceinline__ void cpa16(void* dst, const void* src){
    unsigned d = (unsigned)__cvta_generic_to_shared(dst);
    asm volatile("cp.async.cg.shared.global [%0], [%1], 16;\n" :: "r"(d), "l"(src));
}

// ---------------------------------------------------------------------------
// TN tf32 GEMM body (RNA cvt), used by qkv_proj and out_proj.
// C[m,n] = scale*(sum_k A[m,k]*B[n,k] + bias[n])
// ---------------------------------------------------------------------------
template<int BM,int BN,int BK,int WM,int WN,int NWARPS>
__device__ __forceinline__
void gemm_body(const float* __restrict__ A, int lda,
               const float* __restrict__ B, int ldb,
               float* __restrict__ C, int ldc,
               const float* __restrict__ bias, float scale, int K,
               int m0, int n0)
{
    constexpr int NT  = NWARPS*32;
    constexpr int LA  = BM*BK/(NT*4);
    constexpr int LB  = BN*BK/(NT*4);
    constexpr int WGN = BN/WN;
    constexpr int MI  = WM/16, NI = WN/8;
    constexpr int LDS_ = BK + 4;

    __shared__ unsigned As[2][BM][LDS_];
    __shared__ unsigned Bs[2][BN][LDS_];

    const int tid  = threadIdx.x;
    const int lane = tid & 31, wid = tid >> 5;
    const int wm = wid / WGN, wn = wid % WGN;

    float acc[MI][NI][4] = {};
    float4 ra[LA], rb[LB];

    auto ldtiles = [&](int k0){
        #pragma unroll
        for (int i = 0; i < LA; ++i){
            int idx = tid + i*NT;
            int r = idx / (BK/4), c = (idx % (BK/4)) * 4;
            ra[i] = *(const float4*)(A + (long)(m0+r)*lda + k0 + c);
        }
        #pragma unroll
        for (int i = 0; i < LB; ++i){
            int idx = tid + i*NT;
            int r = idx / (BK/4), c = (idx % (BK/4)) * 4;
            rb[i] = *(const float4*)(B + (long)(n0+r)*ldb + k0 + c);
        }
    };
    auto sttiles = [&](int buf){
        #pragma unroll
        for (int i = 0; i < LA; ++i){
            int idx = tid + i*NT;
            int r = idx / (BK/4), c = (idx % (BK/4)) * 4;
            uint4 u = { f2tf(ra[i].x), f2tf(ra[i].y), f2tf(ra[i].z), f2tf(ra[i].w) };
            *(uint4*)&As[buf][r][c] = u;
        }
        #pragma unroll
        for (int i = 0; i < LB; ++i){
            int idx = tid + i*NT;
            int r = idx / (BK/4), c = (idx % (BK/4)) * 4;
            uint4 u = { f2tf(rb[i].x), f2tf(rb[i].y), f2tf(rb[i].z), f2tf(rb[i].w) };
            *(uint4*)&Bs[buf][r][c] = u;
        }
    };
    auto compute = [&](int buf){
        #pragma unroll
        for (int ks = 0; ks < BK/8; ++ks){
            unsigned af[MI][4], bf[NI][2];
            #pragma unroll
            for (int mi = 0; mi < MI; ++mi){
                int m = wm*WM + mi*16 + (lane>>2);
                int k = ks*8 + (lane&3);
                af[mi][0] = As[buf][m  ][k  ];
                af[mi][1] = As[buf][m+8][k  ];
                af[mi][2] = As[buf][m  ][k+4];
                af[mi][3] = As[buf][m+8][k+4];
            }
            #pragma unroll
            for (int ni = 0; ni < NI; ++ni){
                int n = wn*WN + ni*8 + (lane>>2);
                int k = ks*8 + (lane&3);
                bf[ni][0] = Bs[buf][n][k  ];
                bf[ni][1] = Bs[buf][n][k+4];
            }
            #pragma unroll
            for (int mi = 0; mi < MI; ++mi)
                #pragma unroll
                for (int ni = 0; ni < NI; ++ni)
                    mma8(acc[mi][ni], af[mi], bf[ni]);
        }
    };

    ldtiles(0); sttiles(0); __syncthreads();
    const int nk = K/BK;
    for (int t = 1; t < nk; ++t){
        ldtiles(t*BK);
        compute((t-1)&1);
        sttiles(t&1);
        __syncthreads();
    }
    compute((nk-1)&1);

    #pragma unroll
    for (int mi = 0; mi < MI; ++mi){
        #pragma unroll
        for (int ni = 0; ni < NI; ++ni){
            int m = m0 + wm*WM + mi*16 + (lane>>2);
            int n = n0 + wn*WN + ni*8 + 2*(lane&3);
            float v0 = acc[mi][ni][0], v1 = acc[mi][ni][1];
            float v2 = acc[mi][ni][2], v3 = acc[mi][ni][3];
            float b0 = bias[n], b1 = bias[n+1];
            v0 = (v0+b0)*scale; v1 = (v1+b1)*scale;
            v2 = (v2+b0)*scale; v3 = (v3+b1)*scale;
            *(float2*)(C + (long)m    *ldc + n) = make_float2(v0, v1);
            *(float2*)(C + (long)(m+8)*ldc + n) = make_float2(v2, v3);
        }
    }
}

// Merged Q/K/V projections: grid (8, 64, 3)
__global__ __launch_bounds__(256)
void qkv_proj(const float* __restrict__ q, const float* __restrict__ k, const float* __restrict__ v,
              const float* __restrict__ qw, const float* __restrict__ qb,
              const float* __restrict__ kw, const float* __restrict__ kb,
              const float* __restrict__ vw, const float* __restrict__ vb,
              float* __restrict__ qp, float* __restrict__ kp, float* __restrict__ vp)
{
    const int z = blockIdx.z;
    const float* A  = (z==0)? q  : (z==1)? k  : v;
    const float* W  = (z==0)? qw : (z==1)? kw : vw;
    const float* bi = (z==0)? qb : (z==1)? kb : vb;
    float*       C  = (z==0)? qp : (z==1)? kp : vp;
    const float scale = (z==0)? 0.125f : 1.0f;
    gemm_body<64,128,16,32,32,8>(A, EMB, W, EMB, C, EMB, bi, scale, EMB,
                                 blockIdx.y*64, blockIdx.x*128);
}

// Output projection: grid (8, 64)
__global__ __launch_bounds__(256)
void out_proj(const float* __restrict__ A, const float* __restrict__ W,
              const float* __restrict__ bi, float* __restrict__ C)
{
    gemm_body<64,128,16,32,32,8>(A, EMB, W, EMB, C, EMB, bi, 1.0f, EMB,
                                 blockIdx.y*64, blockIdx.x*128);
}

// ---------------------------------------------------------------------------
// Flash attention v2: block = (hb, q-tile 128). 4 warps, each 32 q-rows (MI=2).
// k-tiles of 32, double-buffered via cp.async (raw f32 -> tf32 truncation for
// K/V; Q and P use RNA cvt). Writes O and per-row (m,l) stats.
// Smem union: Q stage 128x68 <= K[2]32x68 + V[2]32x72 = 8960 words.
// ---------------------------------------------------------------------------
__global__ __launch_bounds__(128)
void flash_attn(const float* __restrict__ qp, const float* __restrict__ kp,
                const float* __restrict__ vp, float* __restrict__ op,
                float* __restrict__ gm, float* __restrict__ gl)
{
    __shared__ __align__(16) unsigned SU[8960];
    const int tid = threadIdx.x, lane = tid&31, w = tid>>5;
    const int hb = blockIdx.x, h = hb&15, b = hb>>4;
    const int q0 = blockIdx.y*128;
    const long base = (long)b*EMB + h*DH;
    const float* Qg = qp + base + (long)q0*(BSZ*EMB);
    const float* Kg = kp + base;
    const float* Vg = vp + base;

    // ---- stage Q (raw), build RNA tf32 A-fragments in registers ----
    for (int i = tid; i < 2048; i += 128){
        int r = i>>4, c = (i&15)*4;
        cpa16(&SU[r*68 + c], Qg + (long)r*(BSZ*EMB) + c);
    }
    asm volatile("cp.async.commit_group;\n");
    asm volatile("cp.async.wait_group 0;\n");
    __syncthreads();

    unsigned Qa[8][2][4];
    {
        const int p = lane>>2, qq = lane&3;
        #pragma unroll
        for (int ks = 0; ks < 8; ++ks)
            #pragma unroll
            for (int mi = 0; mi < 2; ++mi){
                int m = w*32 + mi*16 + p;
                int k = ks*8 + qq;
                Qa[ks][mi][0] = f2tf(__uint_as_float(SU[ m   *68 + k  ]));
                Qa[ks][mi][1] = f2tf(__uint_as_float(SU[(m+8)*68 + k  ]));
                Qa[ks][mi][2] = f2tf(__uint_as_float(SU[ m   *68 + k+4]));
                Qa[ks][mi][3] = f2tf(__uint_as_float(SU[(m+8)*68 + k+4]));
            }
    }
    __syncthreads();

    unsigned* const Kb0 = SU;
    unsigned* const Kb1 = SU + 2176;     // 32*68
    unsigned* const Vb0 = SU + 4352;
    unsigned* const Vb1 = SU + 6656;     // 4352 + 32*72

    auto load_kv = [&](int kt, int sel){
        unsigned* Kb = sel ? Kb1 : Kb0;
        unsigned* Vb = sel ? Vb1 : Vb0;
        const long r0 = (long)kt*32;
        #pragma unroll
        for (int j = 0; j < 4; ++j){
            int cch = tid + j*128;          // 0..511
            int r = cch>>4, cc = (cch&15)*4;
            cpa16(&Kb[r*68 + cc], Kg + (r0+r)*(BSZ*EMB) + cc);
            cpa16(&Vb[r*72 + cc], Vg + (r0+r)*(BSZ*EMB) + cc);
        }
    };

    float m_[2][2] = {{-1e30f,-1e30f},{-1e30f,-1e30f}};
    float l_[2][2] = {};
    float o[2][8][4] = {};

    const int srcA = (lane & ~3) | ((lane&3)>>1);
    const int srcB = srcA + 2;
    const bool osel = (lane & 1);

    load_kv(0, 0);
    asm volatile("cp.async.commit_group;\n");

    for (int t = 0; t < 64; ++t){
        if (t < 63){
            load_kv(t+1, (t+1)&1);
            asm volatile("cp.async.commit_group;\n");
            asm volatile("cp.async.wait_group 1;\n");
        } else {
            asm volatile("cp.async.wait_group 0;\n");
        }
        __syncthreads();

        unsigned* Kb = (t&1) ? Kb1 : Kb0;
        unsigned* Vb = (t&1) ? Vb1 : Vb0;

        // ---- S = Q K^T (warp tile 32 x 32) ----
        float c_[2][4][4] = {};
        #pragma unroll
        for (int ks = 0; ks < 8; ++ks){
            unsigned bf[4][2];
            #pragma unroll
            for (int ni = 0; ni < 4; ++ni){
                int n = ni*8 + (lane>>2);
                int k = ks*8 + (lane&3);
                bf[ni][0] = Kb[n*68 + k];
                bf[ni][1] = Kb[n*68 + k+4];
            }
            #pragma unroll
            for (int mi = 0; mi < 2; ++mi)
                #pragma unroll
                for (int ni = 0; ni < 4; ++ni)
                    mma8(c_[mi][ni], Qa[ks][mi], bf[ni]);
        }

        // ---- online softmax ----
        #pragma unroll
        for (int mi = 0; mi < 2; ++mi){
            float mx0 = -1e30f, mx1 = -1e30f;
            #pragma unroll
            for (int ni = 0; ni < 4; ++ni){
                mx0 = fmaxf(mx0, fmaxf(c_[mi][ni][0], c_[mi][ni][1]));
                mx1 = fmaxf(mx1, fmaxf(c_[mi][ni][2], c_[mi][ni][3]));
            }
            mx0 = fmaxf(mx0, __shfl_xor_sync(0xffffffffu, mx0, 1));
            mx0 = fmaxf(mx0, __shfl_xor_sync(0xffffffffu, mx0, 2));
            mx1 = fmaxf(mx1, __shfl_xor_sync(0xffffffffu, mx1, 1));
            mx1 = fmaxf(mx1, __shfl_xor_sync(0xffffffffu, mx1, 2));
            float mn0 = fmaxf(m_[mi][0], mx0), mn1 = fmaxf(m_[mi][1], mx1);
            float f0 = __expf(m_[mi][0] - mn0), f1 = __expf(m_[mi][1] - mn1);
            l_[mi][0] *= f0; l_[mi][1] *= f1;
            #pragma unroll
            for (int ni = 0; ni < 8; ++ni){
                o[mi][ni][0]*=f0; o[mi][ni][1]*=f0;
                o[mi][ni][2]*=f1; o[mi][ni][3]*=f1;
            }
            float s0 = 0.f, s1 = 0.f;
            #pragma unroll
            for (int ni = 0; ni < 4; ++ni){
                c_[mi][ni][0] = __expf(c_[mi][ni][0]-mn0);
                c_[mi][ni][1] = __expf(c_[mi][ni][1]-mn0);
                c_[mi][ni][2] = __expf(c_[mi][ni][2]-mn1);
                c_[mi][ni][3] = __expf(c_[mi][ni][3]-mn1);
                s0 += c_[mi][ni][0]+c_[mi][ni][1];
                s1 += c_[mi][ni][2]+c_[mi][ni][3];
            }
            s0 += __shfl_xor_sync(0xffffffffu, s0, 1);
            s0 += __shfl_xor_sync(0xffffffffu, s0, 2);
            s1 += __shfl_xor_sync(0xffffffffu, s1, 1);
            s1 += __shfl_xor_sync(0xffffffffu, s1, 2);
            l_[mi][0] += s0; l_[mi][1] += s1;
            m_[mi][0] = mn0; m_[mi][1] = mn1;
        }

        // ---- P @ V (A-frags via quad shuffle, V-frags reused across MI) ----
        #pragma unroll
        for (int ks2 = 0; ks2 < 4; ++ks2){
            unsigned a[2][4];
            #pragma unroll
            for (int mi = 0; mi < 2; ++mi){
                float v00 = __shfl_sync(0xffffffffu, c_[mi][ks2][0], srcA);
                float v01 = __shfl_sync(0xffffffffu, c_[mi][ks2][1], srcA);
                float v10 = __shfl_sync(0xffffffffu, c_[mi][ks2][2], srcA);
                float v11 = __shfl_sync(0xffffffffu, c_[mi][ks2][3], srcA);
                float v40 = __shfl_sync(0xffffffffu, c_[mi][ks2][0], srcB);
                float v41 = __shfl_sync(0xffffffffu, c_[mi][ks2][1], srcB);
                float v50 = __shfl_sync(0xffffffffu, c_[mi][ks2][2], srcB);
                float v51 = __shfl_sync(0xffffffffu, c_[mi][ks2][3], srcB);
                a[mi][0] = f2tf(osel ? v01 : v00);
                a[mi][1] = f2tf(osel ? v11 : v10);
                a[mi][2] = f2tf(osel ? v41 : v40);
                a[mi][3] = f2tf(osel ? v51 : v50);
            }
            #pragma unroll
            for (int ni = 0; ni < 8; ++ni){
                int kk = ks2*8 + (lane&3);
                int n  = ni*8 + (lane>>2);
                unsigned bf[2] = { Vb[kk*72 + n], Vb[(kk+4)*72 + n] };
                mma8(o[0][ni], a[0], bf);
                mma8(o[1][ni], a[1], bf);
            }
        }
        __syncthreads();
    }

    // ---- finalize ----
    float* Og = op + base + (long)q0*(BSZ*EMB);
    #pragma unroll
    for (int mi = 0; mi < 2; ++mi){
        float inv0 = 1.f/l_[mi][0], inv1 = 1.f/l_[mi][1];
        int m = w*32 + mi*16 + (lane>>2);
        #pragma unroll
        for (int ni = 0; ni < 8; ++ni){
            int d = ni*8 + 2*(lane&3);
            *(float2*)(Og + (long)m    *(BSZ*EMB) + d) = make_float2(o[mi][ni][0]*inv0, o[mi][ni][1]*inv0);
            *(float2*)(Og + (long)(m+8)*(BSZ*EMB) + d) = make_float2(o[mi][ni][2]*inv1, o[mi][ni][3]*inv1);
        }
        if ((lane & 3) == 0){
            gm[(long)hb*S_LEN + q0 + m]     = m_[mi][0];
            gm[(long)hb*S_LEN + q0 + m + 8] = m_[mi][1];
            gl[(long)hb*S_LEN + q0 + m]     = l_[mi][0];
            gl[(long)hb*S_LEN + q0 + m + 8] = l_[mi][1];
        }
    }
}

// ---------------------------------------------------------------------------
// attn_avg v2: block = (k-tile 128, q-tile 128, b), 512 thr (16 warps: 8 q-groups
// x 2 k-groups). Loops 16 heads; recomputes QK^T (Q: RNA, K: trunc — identical
// rounding to flash), applies exp(s-m)/l, accumulates in regs, writes once.
// Dynamic smem: Q[128][68] + K[128][68] = 69632 B.
// ---------------------------------------------------------------------------
__global__ __launch_bounds__(512)
void avg_attn(const float* __restrict__ qp, const float* __restrict__ kp,
              const float* __restrict__ gm, const float* __restrict__ gl,
              float* __restrict__ avg)
{
    extern __shared__ unsigned ASH[];
    unsigned* const Qs = ASH;
    unsigned* const Ks = ASH + 8704;     // 128*68
    const int tid = threadIdx.x, lane = tid&31, wid = tid>>5;
    const int wq = wid>>1, wk = wid&1;
    const int k0 = blockIdx.x*128, q0 = blockIdx.y*128, b = blockIdx.z;
    const int rloc = wq*16 + (lane>>2);

    float acc[8][4] = {};

    for (int h = 0; h < NH; ++h){
        const long base = (long)b*EMB + h*DH;
        #pragma unroll
        for (int j = 0; j < 4; ++j){
            int cch = tid + j*512;          // 0..2047
            int r = cch>>4, cc = (cch&15)*4;
            cpa16(&Qs[r*68 + cc], qp + base + (long)(q0+r)*(BSZ*EMB) + cc);
            cpa16(&Ks[r*68 + cc], kp + base + (long)(k0+r)*(BSZ*EMB) + cc);
        }
        asm volatile("cp.async.commit_group;\n");
        asm volatile("cp.async.wait_group 0;\n");
        __syncthreads();

        float c_[8][4] = {};
        #pragma unroll
        for (int ks = 0; ks < 8; ++ks){
            unsigned a[4];
            int k = ks*8 + (lane&3);
            a[0] = f2tf(__uint_as_float(Qs[ rloc   *68 + k  ]));
            a[1] = f2tf(__uint_as_float(Qs[(rloc+8)*68 + k  ]));
            a[2] = f2tf(__uint_as_float(Qs[ rloc   *68 + k+4]));
            a[3] = f2tf(__uint_as_float(Qs[(rloc+8)*68 + k+4]));
            #pragma unroll
            for (int ni = 0; ni < 8; ++ni){
                int n = wk*64 + ni*8 + (lane>>2);
                unsigned bf[2] = { Ks[n*68 + k], Ks[n*68 + k+4] };
                mma8(c_[ni], a, bf);
            }
        }

        const int hb = b*NH + h;
        float mm0 = gm[(long)hb*S_LEN + q0 + rloc];
        float mm1 = gm[(long)hb*S_LEN + q0 + rloc + 8];
        float il0 = 1.f / gl[(long)hb*S_LEN + q0 + rloc];
        float il1 = 1.f / gl[(long)hb*S_LEN + q0 + rloc + 8];
        #pragma unroll
        for (int ni = 0; ni < 8; ++ni){
            acc[ni][0] += __expf(c_[ni][0]-mm0)*il0;
            acc[ni][1] += __expf(c_[ni][1]-mm0)*il0;
            acc[ni][2] += __expf(c_[ni][2]-mm1)*il1;
            acc[ni][3] += __expf(c_[ni][3]-mm1)*il1;
        }
        __syncthreads();
    }

    float* out = avg + (long)b*S2;
    const float s = 1.0f/NH;
    #pragma unroll
    for (int ni = 0; ni < 8; ++ni){
        int kc = k0 + wk*64 + ni*8 + 2*(lane&3);
        *(float2*)(out + (long)(q0+rloc)  *S_LEN + kc) = make_float2(acc[ni][0]*s, acc[ni][1]*s);
        *(float2*)(out + (long)(q0+rloc+8)*S_LEN + kc) = make_float2(acc[ni][2]*s, acc[ni][3]*s);
    }
}

// ---------------------------------------------------------------------------
extern "C" void kernel_launch(void* const* d_in, const int* in_sizes, int n_in,
                              void* d_out, int out_size)
{
    const float* query = (const float*)d_in[0];
    const float* key   = (const float*)d_in[1];
    const float* value = (const float*)d_in[2];
    const float* q_w = (const float*)d_in[3];
    const float* q_b = (const float*)d_in[4];
    const float* k_w = (const float*)d_in[5];
    const float* k_b = (const float*)d_in[6];
    const float* v_w = (const float*)d_in[7];
    const float* v_b = (const float*)d_in[8];
    const float* out_w = (const float*)d_in[9];
    const float* out_b = (const float*)d_in[10];

    float *qp, *kp, *vp, *op, *gm, *gl;
    cudaGetSymbolAddress((void**)&qp, g_Qp);
    cudaGetSymbolAddress((void**)&kp, g_Kp);
    cudaGetSymbolAddress((void**)&vp, g_Vp);
    cudaGetSymbolAddress((void**)&op, g_O);
    cudaGetSymbolAddress((void**)&gm, g_m);
    cudaGetSymbolAddress((void**)&gl, g_l);

    float* Z = (float*)d_out;                          // [S,B,E]
    float* attn_avg = (float*)d_out + (long)MROWS*EMB; // [B,S,S]

    // 1) Q/K/V projections merged: grid (8, 64, 3)
    dim3 gqkv(EMB/128, MROWS/64, 3);
    qkv_proj<<<gqkv, 256>>>(query, key, value, q_w, q_b, k_w, k_b, v_w, v_b, qp, kp, vp);

    // 2) Flash attention
    dim3 gfa(NHEADS, S_LEN/128, 1);
    flash_attn<<<gfa, 128>>>(qp, kp, vp, op, gm, gl);

    // 3) Output projection
    dim3 gop(EMB/128, MROWS/64, 1);
    out_proj<<<gop, 256>>>(op, out_w, out_b, Z);

    // 4) attn_avg via recompute + stored stats (dynamic smem 68KB)
    cudaFuncSetAttribute(avg_attn, cudaFuncAttributeMaxDynamicSharedMemorySize, 69632);
    dim3 gav(S_LEN/128, S_LEN/128, BSZ);
    avg_attn<<<gav, 512, 69632>>>(qp, kp, gm, gl, attn_avg);
}

// round 5
// speedup vs baseline: 2.8794x; 1.0635x over previous
#include <cuda_runtime.h>

#define S_LEN 2048
#define BSZ   2
#define EMB   1024
#define NH    16
#define DH    64
#define MROWS 4096
#define NHEADS 32
#define S2 ((long)S_LEN*S_LEN)

// Scratch (__device__ globals per alloc-free rule)
__device__ float g_Qp[MROWS*EMB];
__device__ float g_Kp[MROWS*EMB];
__device__ float g_Vp[MROWS*EMB];
__device__ float g_O [MROWS*EMB];
__device__ float g_m [NHEADS*S_LEN];
__device__ float g_l [NHEADS*S_LEN];

__device__ __forceinline__ unsigned f2tf(float f){
    unsigned u; asm("cvt.rna.tf32.f32 %0, %1;" : "=r"(u) : "f"(f)); return u;
}
__device__ __forceinline__ void mma8(float* c, const unsigned* a, const unsigned* b){
    asm volatile("mma.sync.aligned.m16n8k8.row.col.f32.tf32.tf32.f32 "
      "{%0,%1,%2,%3}, {%4,%5,%6,%7}, {%8,%9}, {%0,%1,%2,%3};\n"
      : "+f"(c[0]), "+f"(c[1]), "+f"(c[2]), "+f"(c[3])
      : "r"(a[0]), "r"(a[1]), "r"(a[2]), "r"(a[3]), "r"(b[0]), "r"(b[1]));
}
__device__ __forceinline__ void cpa16(void* dst, const void* src){
    unsigned d = (unsigned)__cvta_generic_to_shared(dst);
    asm volatile("cp.async.cg.shared.global [%0], [%1], 16;\n" :: "r"(d), "l"(src));
}

// ---------------------------------------------------------------------------
// TN tf32 GEMM body (RNA cvt), used by qkv_proj and out_proj.
// ---------------------------------------------------------------------------
template<int BM,int BN,int BK,int WM,int WN,int NWARPS>
__device__ __forceinline__
void gemm_body(const float* __restrict__ A, int lda,
               const float* __restrict__ B, int ldb,
               float* __restrict__ C, int ldc,
               const float* __restrict__ bias, float scale, int K,
               int m0, int n0)
{
    constexpr int NT  = NWARPS*32;
    constexpr int LA  = BM*BK/(NT*4);
    constexpr int LB  = BN*BK/(NT*4);
    constexpr int WGN = BN/WN;
    constexpr int MI  = WM/16, NI = WN/8;
    constexpr int LDS_ = BK + 4;

    __shared__ unsigned As[2][BM][LDS_];
    __shared__ unsigned Bs[2][BN][LDS_];

    const int tid  = threadIdx.x;
    const int lane = tid & 31, wid = tid >> 5;
    const int wm = wid / WGN, wn = wid % WGN;

    float acc[MI][NI][4] = {};
    float4 ra[LA], rb[LB];

    auto ldtiles = [&](int k0){
        #pragma unroll
        for (int i = 0; i < LA; ++i){
            int idx = tid + i*NT;
            int r = idx / (BK/4), c = (idx % (BK/4)) * 4;
            ra[i] = *(const float4*)(A + (long)(m0+r)*lda + k0 + c);
        }
        #pragma unroll
        for (int i = 0; i < LB; ++i){
            int idx = tid + i*NT;
            int r = idx / (BK/4), c = (idx % (BK/4)) * 4;
            rb[i] = *(const float4*)(B + (long)(n0+r)*ldb + k0 + c);
        }
    };
    auto sttiles = [&](int buf){
        #pragma unroll
        for (int i = 0; i < LA; ++i){
            int idx = tid + i*NT;
            int r = idx / (BK/4), c = (idx % (BK/4)) * 4;
            uint4 u = { f2tf(ra[i].x), f2tf(ra[i].y), f2tf(ra[i].z), f2tf(ra[i].w) };
            *(uint4*)&As[buf][r][c] = u;
        }
        #pragma unroll
        for (int i = 0; i < LB; ++i){
            int idx = tid + i*NT;
            int r = idx / (BK/4), c = (idx % (BK/4)) * 4;
            uint4 u = { f2tf(rb[i].x), f2tf(rb[i].y), f2tf(rb[i].z), f2tf(rb[i].w) };
            *(uint4*)&Bs[buf][r][c] = u;
        }
    };
    auto compute = [&](int buf){
        #pragma unroll
        for (int ks = 0; ks < BK/8; ++ks){
            unsigned af[MI][4], bf[NI][2];
            #pragma unroll
            for (int mi = 0; mi < MI; ++mi){
                int m = wm*WM + mi*16 + (lane>>2);
                int k = ks*8 + (lane&3);
                af[mi][0] = As[buf][m  ][k  ];
                af[mi][1] = As[buf][m+8][k  ];
                af[mi][2] = As[buf][m  ][k+4];
                af[mi][3] = As[buf][m+8][k+4];
            }
            #pragma unroll
            for (int ni = 0; ni < NI; ++ni){
                int n = wn*WN + ni*8 + (lane>>2);
                int k = ks*8 + (lane&3);
                bf[ni][0] = Bs[buf][n][k  ];
                bf[ni][1] = Bs[buf][n][k+4];
            }
            #pragma unroll
            for (int mi = 0; mi < MI; ++mi)
                #pragma unroll
                for (int ni = 0; ni < NI; ++ni)
                    mma8(acc[mi][ni], af[mi], bf[ni]);
        }
    };

    ldtiles(0); sttiles(0); __syncthreads();
    const int nk = K/BK;
    for (int t = 1; t < nk; ++t){
        ldtiles(t*BK);
        compute((t-1)&1);
        sttiles(t&1);
        __syncthreads();
    }
    compute((nk-1)&1);

    #pragma unroll
    for (int mi = 0; mi < MI; ++mi){
        #pragma unroll
        for (int ni = 0; ni < NI; ++ni){
            int m = m0 + wm*WM + mi*16 + (lane>>2);
            int n = n0 + wn*WN + ni*8 + 2*(lane&3);
            float v0 = acc[mi][ni][0], v1 = acc[mi][ni][1];
            float v2 = acc[mi][ni][2], v3 = acc[mi][ni][3];
            float b0 = bias[n], b1 = bias[n+1];
            v0 = (v0+b0)*scale; v1 = (v1+b1)*scale;
            v2 = (v2+b0)*scale; v3 = (v3+b1)*scale;
            *(float2*)(C + (long)m    *ldc + n) = make_float2(v0, v1);
            *(float2*)(C + (long)(m+8)*ldc + n) = make_float2(v2, v3);
        }
    }
}

// Merged Q/K/V projections: grid (8, 64, 3)
__global__ __launch_bounds__(256)
void qkv_proj(const float* __restrict__ q, const float* __restrict__ k, const float* __restrict__ v,
              const float* __restrict__ qw, const float* __restrict__ qb,
              const float* __restrict__ kw, const float* __restrict__ kb,
              const float* __restrict__ vw, const float* __restrict__ vb,
              float* __restrict__ qp, float* __restrict__ kp, float* __restrict__ vp)
{
    const int z = blockIdx.z;
    const float* A  = (z==0)? q  : (z==1)? k  : v;
    const float* W  = (z==0)? qw : (z==1)? kw : vw;
    const float* bi = (z==0)? qb : (z==1)? kb : vb;
    float*       C  = (z==0)? qp : (z==1)? kp : vp;
    const float scale = (z==0)? 0.125f : 1.0f;
    gemm_body<64,128,16,32,32,8>(A, EMB, W, EMB, C, EMB, bi, scale, EMB,
                                 blockIdx.y*64, blockIdx.x*128);
}

// Output projection: grid (8, 64)
__global__ __launch_bounds__(256)
void out_proj(const float* __restrict__ A, const float* __restrict__ W,
              const float* __restrict__ bi, float* __restrict__ C)
{
    gemm_body<64,128,16,32,32,8>(A, EMB, W, EMB, C, EMB, bi, 1.0f, EMB,
                                 blockIdx.y*64, blockIdx.x*128);
}

// ---------------------------------------------------------------------------
// Flash attention v2.1: block = (hb, q-tile 128). 4 warps (MI=2).
// k-tiles of 32 double-buffered via cp.async. Rescale-skip when max unchanged.
// ---------------------------------------------------------------------------
__global__ __launch_bounds__(128)
void flash_attn(const float* __restrict__ qp, const float* __restrict__ kp,
                const float* __restrict__ vp, float* __restrict__ op,
                float* __restrict__ gm, float* __restrict__ gl)
{
    __shared__ __align__(16) unsigned SU[8960];
    const int tid = threadIdx.x, lane = tid&31, w = tid>>5;
    const int hb = blockIdx.x, h = hb&15, b = hb>>4;
    const int q0 = blockIdx.y*128;
    const long base = (long)b*EMB + h*DH;
    const float* Qg = qp + base + (long)q0*(BSZ*EMB);
    const float* Kg = kp + base;
    const float* Vg = vp + base;

    // stage Q raw, build RNA tf32 A-fragments
    for (int i = tid; i < 2048; i += 128){
        int r = i>>4, c = (i&15)*4;
        cpa16(&SU[r*68 + c], Qg + (long)r*(BSZ*EMB) + c);
    }
    asm volatile("cp.async.commit_group;\n");
    asm volatile("cp.async.wait_group 0;\n");
    __syncthreads();

    unsigned Qa[8][2][4];
    {
        const int p = lane>>2, qq = lane&3;
        #pragma unroll
        for (int ks = 0; ks < 8; ++ks)
            #pragma unroll
            for (int mi = 0; mi < 2; ++mi){
                int m = w*32 + mi*16 + p;
                int k = ks*8 + qq;
                Qa[ks][mi][0] = f2tf(__uint_as_float(SU[ m   *68 + k  ]));
                Qa[ks][mi][1] = f2tf(__uint_as_float(SU[(m+8)*68 + k  ]));
                Qa[ks][mi][2] = f2tf(__uint_as_float(SU[ m   *68 + k+4]));
                Qa[ks][mi][3] = f2tf(__uint_as_float(SU[(m+8)*68 + k+4]));
            }
    }
    __syncthreads();

    unsigned* const Kb0 = SU;
    unsigned* const Kb1 = SU + 2176;
    unsigned* const Vb0 = SU + 4352;
    unsigned* const Vb1 = SU + 6656;

    auto load_kv = [&](int kt, int sel){
        unsigned* Kb = sel ? Kb1 : Kb0;
        unsigned* Vb = sel ? Vb1 : Vb0;
        const long r0 = (long)kt*32;
        #pragma unroll
        for (int j = 0; j < 4; ++j){
            int cch = tid + j*128;
            int r = cch>>4, cc = (cch&15)*4;
            cpa16(&Kb[r*68 + cc], Kg + (r0+r)*(BSZ*EMB) + cc);
            cpa16(&Vb[r*72 + cc], Vg + (r0+r)*(BSZ*EMB) + cc);
        }
    };

    float m_[2][2] = {{-1e30f,-1e30f},{-1e30f,-1e30f}};
    float l_[2][2] = {};
    float o[2][8][4] = {};

    const int srcA = (lane & ~3) | ((lane&3)>>1);
    const int srcB = srcA + 2;
    const bool osel = (lane & 1);

    load_kv(0, 0);
    asm volatile("cp.async.commit_group;\n");

    for (int t = 0; t < 64; ++t){
        if (t < 63){
            load_kv(t+1, (t+1)&1);
            asm volatile("cp.async.commit_group;\n");
            asm volatile("cp.async.wait_group 1;\n");
        } else {
            asm volatile("cp.async.wait_group 0;\n");
        }
        __syncthreads();

        unsigned* Kb = (t&1) ? Kb1 : Kb0;
        unsigned* Vb = (t&1) ? Vb1 : Vb0;

        // S = Q K^T
        float c_[2][4][4] = {};
        #pragma unroll
        for (int ks = 0; ks < 8; ++ks){
            unsigned bf[4][2];
            #pragma unroll
            for (int ni = 0; ni < 4; ++ni){
                int n = ni*8 + (lane>>2);
                int k = ks*8 + (lane&3);
                bf[ni][0] = Kb[n*68 + k];
                bf[ni][1] = Kb[n*68 + k+4];
            }
            #pragma unroll
            for (int mi = 0; mi < 2; ++mi)
                #pragma unroll
                for (int ni = 0; ni < 4; ++ni)
                    mma8(c_[mi][ni], Qa[ks][mi], bf[ni]);
        }

        // online softmax with rescale-skip
        #pragma unroll
        for (int mi = 0; mi < 2; ++mi){
            float mx0 = -1e30f, mx1 = -1e30f;
            #pragma unroll
            for (int ni = 0; ni < 4; ++ni){
                mx0 = fmaxf(mx0, fmaxf(c_[mi][ni][0], c_[mi][ni][1]));
                mx1 = fmaxf(mx1, fmaxf(c_[mi][ni][2], c_[mi][ni][3]));
            }
            mx0 = fmaxf(mx0, __shfl_xor_sync(0xffffffffu, mx0, 1));
            mx0 = fmaxf(mx0, __shfl_xor_sync(0xffffffffu, mx0, 2));
            mx1 = fmaxf(mx1, __shfl_xor_sync(0xffffffffu, mx1, 1));
            mx1 = fmaxf(mx1, __shfl_xor_sync(0xffffffffu, mx1, 2));
            float mn0 = fmaxf(m_[mi][0], mx0), mn1 = fmaxf(m_[mi][1], mx1);
            if (!__all_sync(0xffffffffu, (mn0 == m_[mi][0]) & (mn1 == m_[mi][1]))){
                float f0 = __expf(m_[mi][0] - mn0), f1 = __expf(m_[mi][1] - mn1);
                l_[mi][0] *= f0; l_[mi][1] *= f1;
                #pragma unroll
                for (int ni = 0; ni < 8; ++ni){
                    o[mi][ni][0]*=f0; o[mi][ni][1]*=f0;
                    o[mi][ni][2]*=f1; o[mi][ni][3]*=f1;
                }
                m_[mi][0] = mn0; m_[mi][1] = mn1;
            }
            float s0 = 0.f, s1 = 0.f;
            #pragma unroll
            for (int ni = 0; ni < 4; ++ni){
                c_[mi][ni][0] = __expf(c_[mi][ni][0]-m_[mi][0]);
                c_[mi][ni][1] = __expf(c_[mi][ni][1]-m_[mi][0]);
                c_[mi][ni][2] = __expf(c_[mi][ni][2]-m_[mi][1]);
                c_[mi][ni][3] = __expf(c_[mi][ni][3]-m_[mi][1]);
                s0 += c_[mi][ni][0]+c_[mi][ni][1];
                s1 += c_[mi][ni][2]+c_[mi][ni][3];
            }
            s0 += __shfl_xor_sync(0xffffffffu, s0, 1);
            s0 += __shfl_xor_sync(0xffffffffu, s0, 2);
            s1 += __shfl_xor_sync(0xffffffffu, s1, 1);
            s1 += __shfl_xor_sync(0xffffffffu, s1, 2);
            l_[mi][0] += s0; l_[mi][1] += s1;
        }

        // P @ V
        #pragma unroll
        for (int ks2 = 0; ks2 < 4; ++ks2){
            unsigned a[2][4];
            #pragma unroll
            for (int mi = 0; mi < 2; ++mi){
                float v00 = __shfl_sync(0xffffffffu, c_[mi][ks2][0], srcA);
                float v01 = __shfl_sync(0xffffffffu, c_[mi][ks2][1], srcA);
                float v10 = __shfl_sync(0xffffffffu, c_[mi][ks2][2], srcA);
                float v11 = __shfl_sync(0xffffffffu, c_[mi][ks2][3], srcA);
                float v40 = __shfl_sync(0xffffffffu, c_[mi][ks2][0], srcB);
                float v41 = __shfl_sync(0xffffffffu, c_[mi][ks2][1], srcB);
                float v50 = __shfl_sync(0xffffffffu, c_[mi][ks2][2], srcB);
                float v51 = __shfl_sync(0xffffffffu, c_[mi][ks2][3], srcB);
                a[mi][0] = f2tf(osel ? v01 : v00);
                a[mi][1] = f2tf(osel ? v11 : v10);
                a[mi][2] = f2tf(osel ? v41 : v40);
                a[mi][3] = f2tf(osel ? v51 : v50);
            }
            #pragma unroll
            for (int ni = 0; ni < 8; ++ni){
                int kk = ks2*8 + (lane&3);
                int n  = ni*8 + (lane>>2);
                unsigned bf[2] = { Vb[kk*72 + n], Vb[(kk+4)*72 + n] };
                mma8(o[0][ni], a[0], bf);
                mma8(o[1][ni], a[1], bf);
            }
        }
        __syncthreads();
    }

    float* Og = op + base + (long)q0*(BSZ*EMB);
    #pragma unroll
    for (int mi = 0; mi < 2; ++mi){
        float inv0 = 1.f/l_[mi][0], inv1 = 1.f/l_[mi][1];
        int m = w*32 + mi*16 + (lane>>2);
        #pragma unroll
        for (int ni = 0; ni < 8; ++ni){
            int d = ni*8 + 2*(lane&3);
            *(float2*)(Og + (long)m    *(BSZ*EMB) + d) = make_float2(o[mi][ni][0]*inv0, o[mi][ni][1]*inv0);
            *(float2*)(Og + (long)(m+8)*(BSZ*EMB) + d) = make_float2(o[mi][ni][2]*inv1, o[mi][ni][3]*inv1);
        }
        if ((lane & 3) == 0){
            gm[(long)hb*S_LEN + q0 + m]     = m_[mi][0];
            gm[(long)hb*S_LEN + q0 + m + 8] = m_[mi][1];
            gl[(long)hb*S_LEN + q0 + m]     = l_[mi][0];
            gl[(long)hb*S_LEN + q0 + m + 8] = l_[mi][1];
        }
    }
}

// ---------------------------------------------------------------------------
// attn_avg v3: double-buffered head pipeline.
// block = (k-tile 128, q-tile 128, b), 512 thr. Dynamic smem 139264 B:
// 2 buffers x (Q[128][68] + K[128][68]). Prefetch head h+1 during compute of h.
// ---------------------------------------------------------------------------
__global__ __launch_bounds__(512)
void avg_attn(const float* __restrict__ qp, const float* __restrict__ kp,
              const float* __restrict__ gm, const float* __restrict__ gl,
              float* __restrict__ avg)
{
    extern __shared__ unsigned ASH[];
    const int tid = threadIdx.x, lane = tid&31, wid = tid>>5;
    const int wq = wid>>1, wk = wid&1;
    const int k0 = blockIdx.x*128, q0 = blockIdx.y*128, b = blockIdx.z;
    const int rloc = wq*16 + (lane>>2);

    auto stage = [&](int h, int sel){
        unsigned* Qs = ASH + sel*17408;
        unsigned* Ks = Qs + 8704;
        const long base = (long)b*EMB + h*DH;
        #pragma unroll
        for (int j = 0; j < 4; ++j){
            int cch = tid + j*512;
            int r = cch>>4, cc = (cch&15)*4;
            cpa16(&Qs[r*68 + cc], qp + base + (long)(q0+r)*(BSZ*EMB) + cc);
            cpa16(&Ks[r*68 + cc], kp + base + (long)(k0+r)*(BSZ*EMB) + cc);
        }
        asm volatile("cp.async.commit_group;\n");
    };

    float acc[8][4] = {};

    stage(0, 0);
    for (int h = 0; h < NH; ++h){
        if (h < NH-1){
            stage(h+1, (h+1)&1);
            asm volatile("cp.async.wait_group 1;\n");
        } else {
            asm volatile("cp.async.wait_group 0;\n");
        }
        __syncthreads();

        unsigned* Qs = ASH + (h&1)*17408;
        unsigned* Ks = Qs + 8704;

        float c_[8][4] = {};
        #pragma unroll
        for (int ks = 0; ks < 8; ++ks){
            unsigned a[4];
            int k = ks*8 + (lane&3);
            a[0] = f2tf(__uint_as_float(Qs[ rloc   *68 + k  ]));
            a[1] = f2tf(__uint_as_float(Qs[(rloc+8)*68 + k  ]));
            a[2] = f2tf(__uint_as_float(Qs[ rloc   *68 + k+4]));
            a[3] = f2tf(__uint_as_float(Qs[(rloc+8)*68 + k+4]));
            #pragma unroll
            for (int ni = 0; ni < 8; ++ni){
                int n = wk*64 + ni*8 + (lane>>2);
                unsigned bf[2] = { Ks[n*68 + k], Ks[n*68 + k+4] };
                mma8(c_[ni], a, bf);
            }
        }

        const int hb = b*NH + h;
        float mm0 = gm[(long)hb*S_LEN + q0 + rloc];
        float mm1 = gm[(long)hb*S_LEN + q0 + rloc + 8];
        float il0 = 1.f / gl[(long)hb*S_LEN + q0 + rloc];
        float il1 = 1.f / gl[(long)hb*S_LEN + q0 + rloc + 8];
        #pragma unroll
        for (int ni = 0; ni < 8; ++ni){
            acc[ni][0] += __expf(c_[ni][0]-mm0)*il0;
            acc[ni][1] += __expf(c_[ni][1]-mm0)*il0;
            acc[ni][2] += __expf(c_[ni][2]-mm1)*il1;
            acc[ni][3] += __expf(c_[ni][3]-mm1)*il1;
        }
        __syncthreads();
    }

    float* out = avg + (long)b*S2;
    const float s = 1.0f/NH;
    #pragma unroll
    for (int ni = 0; ni < 8; ++ni){
        int kc = k0 + wk*64 + ni*8 + 2*(lane&3);
        *(float2*)(out + (long)(q0+rloc)  *S_LEN + kc) = make_float2(acc[ni][0]*s, acc[ni][1]*s);
        *(float2*)(out + (long)(q0+rloc+8)*S_LEN + kc) = make_float2(acc[ni][2]*s, acc[ni][3]*s);
    }
}

// ---------------------------------------------------------------------------
extern "C" void kernel_launch(void* const* d_in, const int* in_sizes, int n_in,
                              void* d_out, int out_size)
{
    const float* query = (const float*)d_in[0];
    const float* key   = (const float*)d_in[1];
    const float* value = (const float*)d_in[2];
    const float* q_w = (const float*)d_in[3];
    const float* q_b = (const float*)d_in[4];
    const float* k_w = (const float*)d_in[5];
    const float* k_b = (const float*)d_in[6];
    const float* v_w = (const float*)d_in[7];
    const float* v_b = (const float*)d_in[8];
    const float* out_w = (const float*)d_in[9];
    const float* out_b = (const float*)d_in[10];

    float *qp, *kp, *vp, *op, *gm, *gl;
    cudaGetSymbolAddress((void**)&qp, g_Qp);
    cudaGetSymbolAddress((void**)&kp, g_Kp);
    cudaGetSymbolAddress((void**)&vp, g_Vp);
    cudaGetSymbolAddress((void**)&op, g_O);
    cudaGetSymbolAddress((void**)&gm, g_m);
    cudaGetSymbolAddress((void**)&gl, g_l);

    float* Z = (float*)d_out;                          // [S,B,E]
    float* attn_avg = (float*)d_out + (long)MROWS*EMB; // [B,S,S]

    // 1) Q/K/V projections merged
    dim3 gqkv(EMB/128, MROWS/64, 3);
    qkv_proj<<<gqkv, 256>>>(query, key, value, q_w, q_b, k_w, k_b, v_w, v_b, qp, kp, vp);

    // 2) Flash attention
    dim3 gfa(NHEADS, S_LEN/128, 1);
    flash_attn<<<gfa, 128>>>(qp, kp, vp, op, gm, gl);

    // 3) Output projection
    dim3 gop(EMB/128, MROWS/64, 1);
    out_proj<<<gop, 256>>>(op, out_w, out_b, Z);

    // 4) attn_avg, double-buffered head pipeline (dynamic smem 136KB)
    cudaFuncSetAttribute(avg_attn, cudaFuncAttributeMaxDynamicSharedMemorySize, 139264);
    dim3 gav(S_LEN/128, S_LEN/128, BSZ);
    avg_attn<<<gav, 512, 139264>>>(qp, kp, gm, gl, attn_avg);
}